// round 1
// baseline (speedup 1.0000x reference)
#include <cuda_runtime.h>

#define N_TOK 2048
#define K_TOK 128
#define D_DIM 768
#define H_DIM 512

// Scratch (device globals: no allocation allowed in kernel_launch)
__device__ float g_img[N_TOK * H_DIM];    // [n][h]  img @ W1[:D]
__device__ float g_txtT[H_DIM * K_TOK];   // [h][k]  (txt @ W1[D:]) + b1, transposed

// ---------- packed f32x2 helpers ----------
__device__ __forceinline__ unsigned long long pack2(float lo, float hi) {
    unsigned long long r;
    asm("mov.b64 %0, {%1, %2};" : "=l"(r) : "f"(lo), "f"(hi));
    return r;
}
__device__ __forceinline__ void unpack2(unsigned long long v, float& lo, float& hi) {
    asm("mov.b64 {%0, %1}, %2;" : "=f"(lo), "=f"(hi) : "l"(v));
}
__device__ __forceinline__ void fma2(unsigned long long& d, unsigned long long a, unsigned long long b) {
    asm("fma.rn.f32x2 %0, %1, %2, %0;" : "+l"(d) : "l"(a), "l"(b));
}

// ---------- projection GEMM: C[M,512] = A[M,768] @ W[768,512] ----------
// BM=64, BN=64, BK=16, 128 threads, per-thread tile 4m x 8n (f32x2-packed n-pairs)
// MODE 0: store normal into g_img[m*512+n]
// MODE 1: add bias, store transposed into g_txtT[n*128+m]
template <int MODE>
__global__ __launch_bounds__(128) void proj_kernel(
    const float* __restrict__ A, const float* __restrict__ W,
    const float* __restrict__ bias)
{
    __shared__ float As[64][20];   // [m][k], stride 20 keeps float4 STS aligned
    __shared__ float Ws[16][64];   // [k][n]

    const int t  = threadIdx.x;
    const int tx = t & 7;          // n: 8 groups of 8
    const int ty = t >> 3;         // m: 16 groups of 4
    const int m0 = blockIdx.y * 64;
    const int n0 = blockIdx.x * 64;

    const int fid0 = t, fid1 = 128 + t;
    const int ar0 = fid0 >> 2, ac0 = (fid0 & 3) << 2;
    const int ar1 = fid1 >> 2, ac1 = (fid1 & 3) << 2;
    const int wr0 = fid0 >> 4, wc0 = (fid0 & 15) << 2;
    const int wr1 = fid1 >> 4, wc1 = (fid1 & 15) << 2;

    // prefetch tile 0
    float4 pa0 = *(const float4*)&A[(m0 + ar0) * D_DIM + ac0];
    float4 pa1 = *(const float4*)&A[(m0 + ar1) * D_DIM + ac1];
    float4 pw0 = *(const float4*)&W[wr0 * H_DIM + n0 + wc0];
    float4 pw1 = *(const float4*)&W[wr1 * H_DIM + n0 + wc1];

    unsigned long long acc[4][4];
    #pragma unroll
    for (int i = 0; i < 4; i++)
        #pragma unroll
        for (int p = 0; p < 4; p++) acc[i][p] = 0ull;

    const int NIT = D_DIM / 16;  // 48
    for (int kt = 0; kt < NIT; kt++) {
        *(float4*)&As[ar0][ac0] = pa0;
        *(float4*)&As[ar1][ac1] = pa1;
        *(float4*)&Ws[wr0][wc0] = pw0;
        *(float4*)&Ws[wr1][wc1] = pw1;
        __syncthreads();

        if (kt + 1 < NIT) {  // register double-buffer: hide LDG behind compute
            const int k0 = (kt + 1) * 16;
            pa0 = *(const float4*)&A[(m0 + ar0) * D_DIM + k0 + ac0];
            pa1 = *(const float4*)&A[(m0 + ar1) * D_DIM + k0 + ac1];
            pw0 = *(const float4*)&W[(k0 + wr0) * H_DIM + n0 + wc0];
            pw1 = *(const float4*)&W[(k0 + wr1) * H_DIM + n0 + wc1];
        }

        #pragma unroll
        for (int kk = 0; kk < 16; kk++) {
            const unsigned long long* bp =
                (const unsigned long long*)&Ws[kk][tx << 3];
            unsigned long long b0 = bp[0], b1 = bp[1], b2r = bp[2], b3 = bp[3];
            #pragma unroll
            for (int i = 0; i < 4; i++) {
                float a = As[(ty << 2) + i][kk];
                unsigned long long a2 = pack2(a, a);
                fma2(acc[i][0], a2, b0);
                fma2(acc[i][1], a2, b1);
                fma2(acc[i][2], a2, b2r);
                fma2(acc[i][3], a2, b3);
            }
        }
        __syncthreads();
    }

    #pragma unroll
    for (int i = 0; i < 4; i++) {
        const int m = m0 + (ty << 2) + i;
        if (MODE == 0) {
            float4 v0, v1;
            unpack2(acc[i][0], v0.x, v0.y);
            unpack2(acc[i][1], v0.z, v0.w);
            unpack2(acc[i][2], v1.x, v1.y);
            unpack2(acc[i][3], v1.z, v1.w);
            *(float4*)&g_img[m * H_DIM + n0 + (tx << 3)]     = v0;
            *(float4*)&g_img[m * H_DIM + n0 + (tx << 3) + 4] = v1;
        } else {
            #pragma unroll
            for (int p = 0; p < 4; p++) {
                float lo, hi;
                unpack2(acc[i][p], lo, hi);
                const int n = n0 + (tx << 3) + (p << 1);
                g_txtT[n * K_TOK + m]       = lo + bias[n];
                g_txtT[(n + 1) * K_TOK + m] = hi + bias[n + 1];
            }
        }
    }
}

// ---------- fused relu-dot: out[n,k] = b2 + sum_h relu(img[n,h]+txtT[h,k])*W2[h]
// Block: 16 n x 128 k, 256 threads, per-thread 2n x 4k. H chunked by 64.
__global__ __launch_bounds__(256) void fused_kernel(
    const float* __restrict__ W2, const float* __restrict__ b2,
    float* __restrict__ out)
{
    __shared__ float t_s[64][128];   // [h][k]  32 KB
    __shared__ float a_s[64][17];    // [h][n]  padded vs 2-way STS conflicts
    __shared__ float w2s[H_DIM];

    const int t  = threadIdx.x;
    const int tx = t & 31;           // k: 32 groups of 4
    const int ty = t >> 5;           // n: 8 groups of 2
    const int nbase = blockIdx.x * 16;

    w2s[t]       = W2[t];
    w2s[t + 256] = W2[t + 256];

    float acc[2][4];
    #pragma unroll
    for (int j = 0; j < 2; j++)
        #pragma unroll
        for (int p = 0; p < 4; p++) acc[j][p] = 0.f;

    const int an  = t >> 4;          // 0..15 (n row for a-tile load)
    const int ah4 = t & 15;          // float4 index along h

    for (int hc = 0; hc < 8; hc++) {
        const int hb = hc * 64;
        __syncthreads();
        // a tile: 16n x 64h (float4 along h, transpose into [h][n])
        {
            float4 av = *(const float4*)&g_img[(nbase + an) * H_DIM + hb + (ah4 << 2)];
            a_s[(ah4 << 2) + 0][an] = av.x;
            a_s[(ah4 << 2) + 1][an] = av.y;
            a_s[(ah4 << 2) + 2][an] = av.z;
            a_s[(ah4 << 2) + 3][an] = av.w;
        }
        // t tile: 64h x 128k, already [h][k] in gmem -> conflict-free float4
        #pragma unroll
        for (int i = 0; i < 8; i++) {
            const int fid = i * 256 + t;
            const int h = fid >> 5, k4 = fid & 31;
            *(float4*)&t_s[h][k4 << 2] =
                *(const float4*)&g_txtT[(hb + h) * K_TOK + (k4 << 2)];
        }
        __syncthreads();

        #pragma unroll 8
        for (int h = 0; h < 64; h++) {
            const float w  = w2s[hb + h];
            const float a0 = a_s[h][(ty << 1)];
            const float a1 = a_s[h][(ty << 1) + 1];
            const float4 tv = *(const float4*)&t_s[h][tx << 2];
            acc[0][0] += fmaxf(a0 + tv.x, 0.f) * w;
            acc[0][1] += fmaxf(a0 + tv.y, 0.f) * w;
            acc[0][2] += fmaxf(a0 + tv.z, 0.f) * w;
            acc[0][3] += fmaxf(a0 + tv.w, 0.f) * w;
            acc[1][0] += fmaxf(a1 + tv.x, 0.f) * w;
            acc[1][1] += fmaxf(a1 + tv.y, 0.f) * w;
            acc[1][2] += fmaxf(a1 + tv.z, 0.f) * w;
            acc[1][3] += fmaxf(a1 + tv.w, 0.f) * w;
        }
    }

    const float bb = b2[0];
    #pragma unroll
    for (int j = 0; j < 2; j++) {
        float4 v;
        v.x = acc[j][0] + bb;
        v.y = acc[j][1] + bb;
        v.z = acc[j][2] + bb;
        v.w = acc[j][3] + bb;
        *(float4*)&out[(nbase + (ty << 1) + j) * K_TOK + (tx << 2)] = v;
    }
}

extern "C" void kernel_launch(void* const* d_in, const int* in_sizes, int n_in,
                              void* d_out, int out_size) {
    const float* img = (const float*)d_in[0];   // (2048, 768)
    const float* txt = (const float*)d_in[1];   // (128, 768)
    const float* W1  = (const float*)d_in[2];   // (1536, 512)
    const float* b1  = (const float*)d_in[3];   // (512,)
    const float* W2  = (const float*)d_in[4];   // (512, 1)
    const float* b2  = (const float*)d_in[5];   // (1,)
    float* out = (float*)d_out;                 // (2048, 128)

    // txt projection (+b1, transposed store) — tiny, launch first
    proj_kernel<1><<<dim3(H_DIM / 64, K_TOK / 64), 128>>>(txt, W1 + D_DIM * H_DIM, b1);
    // img projection — the big GEMM
    proj_kernel<0><<<dim3(H_DIM / 64, N_TOK / 64), 128>>>(img, W1, nullptr);
    // fused relu-dot epilogue
    fused_kernel<<<N_TOK / 16, 256>>>(W2, b2, out);
}